// round 9
// baseline (speedup 1.0000x reference)
#include <cuda_runtime.h>
#include <cuda_bf16.h>

#define RES 7
#define NROI 1024
#define NCH 256
#define CPI 4              // channels staged per iteration
#define CHUNK 64           // channels per block
#define NIT (CHUNK / CPI)  // 16 iterations
#define PSZ 784            // 28x28 packed taps per channel

// ---------------- per-roi precomputed tables ----------------
__device__ int2  g_lb[NROI];            // lvl, batch
__device__ int   g_yoff[NROI][28];      // packed tap row offsets (row*W)
__device__ int   g_xoff[NROI][28];      // packed tap col offsets
__device__ float g_wy[NROI][28];        // y tap weights (*0.5, validity folded)
__device__ float g_wx[NROI][28];        // x tap weights (*0.5, validity folded)

__device__ __forceinline__ void samp(float v, int size,
                                     int& lo, int& hi, float& wl, float& wh) {
    bool valid = (v >= -1.0f) && (v <= (float)size);
    float v0 = fmaxf(v, 0.0f);
    int l = (int)floorf(v0);
    float fr;
    if (l >= size - 1) { l = size - 1; hi = size - 1; fr = 0.0f; }
    else               { hi = l + 1; fr = v0 - (float)l; }
    lo = l;
    wl = valid ? (1.0f - fr) : 0.0f;
    wh = valid ? fr : 0.0f;
}

__global__ void setup_kernel(const float* __restrict__ p0,
                             const float* __restrict__ p1) {
    int r = blockIdx.x * blockDim.x + threadIdx.x;
    if (r >= NROI) return;
    const float* p = (r < 512) ? (p0 + r * 4) : (p1 + (r - 512) * 4);
    float x1 = p[0], y1 = p[1], x2 = p[2], y2 = p[3];
    float area = (x2 - x1 + 1.0f) * (y2 - y1 + 1.0f);
    float sz = sqrtf(area);
    float lv = floorf(4.0f + log2f(sz / 224.0f + 1e-6f));
    lv = fminf(fmaxf(lv, 2.0f), 5.0f);
    int lvl = (int)lv - 2;
    float scale = 0.25f / (float)(1 << lvl);
    int H, W;
    switch (lvl) {
        case 0:  H = 200; W = 200; break;
        case 1:  H = 100; W = 100; break;
        case 2:  H = 50;  W = 50;  break;
        default: H = 25;  W = 25;  break;
    }
    float x1s = x1 * scale, y1s = y1 * scale;
    float rw = fmaxf(x2 * scale - x1s, 1.0f);
    float rh = fmaxf(y2 * scale - y1s, 1.0f);
    float bw = rw / 7.0f, bh = rh / 7.0f;

    g_lb[r] = make_int2(lvl, (r < 512) ? 0 : 1);

#pragma unroll
    for (int s = 0; s < 14; s++) {
        {   // y sample s
            float v = y1s + ((float)s + 0.5f) * 0.5f * bh;
            int lo, hi; float wl, wh;
            samp(v, H, lo, hi, wl, wh);
            g_yoff[r][2 * s]     = lo * W;
            g_yoff[r][2 * s + 1] = hi * W;
            g_wy[r][2 * s]       = wl * 0.5f;
            g_wy[r][2 * s + 1]   = wh * 0.5f;
        }
        {   // x sample s
            float v = x1s + ((float)s + 0.5f) * 0.5f * bw;
            int lo, hi; float wl, wh;
            samp(v, W, lo, hi, wl, wh);
            g_xoff[r][2 * s]     = lo;
            g_xoff[r][2 * s + 1] = hi;
            g_wx[r][2 * s]       = wl * 0.5f;
            g_wx[r][2 * s + 1]   = wh * 0.5f;
        }
    }
}

// grid = (4, NROI): blockIdx.y = roi, blockIdx.x = 64-channel chunk.
// Double-buffered: stage 4 channels' 28x28 packed tap patches, compute 4x49
// outputs as contiguous 4x4 weighted blocks (float4 LDS).
__global__ __launch_bounds__(256) void pool_kernel(
    const float* __restrict__ f0, const float* __restrict__ f1,
    const float* __restrict__ f2, const float* __restrict__ f3,
    float* __restrict__ out) {

    __shared__ __align__(16) float bufs[2 * CPI * PSZ];   // 25 KB
    __shared__ int   yoffS[28], xoffS[28];
    __shared__ float wyS[28];
    __shared__ __align__(16) float wxS[28];

    const int roi = blockIdx.y;
    const int tid = threadIdx.x;

    if (tid < 28) {
        yoffS[tid] = g_yoff[roi][tid];
        xoffS[tid] = g_xoff[roi][tid];
        wyS[tid]   = g_wy[roi][tid];
        wxS[tid]   = g_wx[roi][tid];
    }

    const int2 lb = g_lb[roi];
    const float* base; int HW;
    switch (lb.x) {
        case 0:  base = f0; HW = 200 * 200; break;
        case 1:  base = f1; HW = 100 * 100; break;
        case 2:  base = f2; HW = 50 * 50;   break;
        default: base = f3; HW = 25 * 25;   break;
    }
    const float* gbase = base + (size_t)lb.y * NCH * HW;
    const int chunk = blockIdx.x * CHUNK;

    __syncthreads();   // tables ready

    // ---- hoisted compute-thread state ----
    const bool comp = tid < CPI * 49;
    int c_ch = 0, bin = 0, poff = 0;
    float4 wx4 = make_float4(0.f, 0.f, 0.f, 0.f);
    float wy0 = 0.f, wy1 = 0.f, wy2 = 0.f, wy3 = 0.f;
    if (comp) {
        c_ch = tid / 49; bin = tid - c_ch * 49;
        int py = bin / 7, px = bin - py * 7;
        poff = c_ch * PSZ + py * 112 + px * 4;
        wx4 = *(const float4*)(wxS + 4 * px);
        wy0 = wyS[4 * py];     wy1 = wyS[4 * py + 1];
        wy2 = wyS[4 * py + 2]; wy3 = wyS[4 * py + 3];
    }

    // ---- stage iteration 0 ----
    {
        float* dst = bufs;
#pragma unroll
        for (int ch = 0; ch < CPI; ch++) {
            const float* src = gbase + (size_t)(chunk + ch) * HW;
            float* d = dst + ch * PSZ;
            for (int t = tid; t < PSZ; t += 256) {
                int r = t / 28, c2 = t - r * 28;
                d[t] = __ldg(src + yoffS[r] + xoffS[c2]);
            }
        }
    }

    for (int it = 0; it < NIT; it++) {
        __syncthreads();   // stage(it) visible; compute(it-1) done
        float* cur = bufs + (it & 1) * (CPI * PSZ);
        // stage next iteration into the other buffer (LDG latency hides
        // under this iteration's compute)
        if (it + 1 < NIT) {
            float* nxt = bufs + ((it + 1) & 1) * (CPI * PSZ);
            const int c0n = chunk + (it + 1) * CPI;
#pragma unroll
            for (int ch = 0; ch < CPI; ch++) {
                const float* src = gbase + (size_t)(c0n + ch) * HW;
                float* d = nxt + ch * PSZ;
                for (int t = tid; t < PSZ; t += 256) {
                    int r = t / 28, c2 = t - r * 28;
                    d[t] = __ldg(src + yoffS[r] + xoffS[c2]);
                }
            }
        }
        // compute this iteration
        if (comp) {
            const float* p = cur + poff;
            float4 v0 = *(const float4*)(p);
            float4 v1 = *(const float4*)(p + 28);
            float4 v2 = *(const float4*)(p + 56);
            float4 v3 = *(const float4*)(p + 84);
            float acc =
                wy0 * (v0.x * wx4.x + v0.y * wx4.y + v0.z * wx4.z + v0.w * wx4.w) +
                wy1 * (v1.x * wx4.x + v1.y * wx4.y + v1.z * wx4.z + v1.w * wx4.w) +
                wy2 * (v2.x * wx4.x + v2.y * wx4.y + v2.z * wx4.z + v2.w * wx4.w) +
                wy3 * (v3.x * wx4.x + v3.y * wx4.y + v3.z * wx4.z + v3.w * wx4.w);
            int c = chunk + it * CPI + c_ch;
            out[((size_t)roi * NCH + c) * 49 + bin] = acc;
        }
    }
}

extern "C" void kernel_launch(void* const* d_in, const int* in_sizes, int n_in,
                              void* d_out, int out_size) {
    const float* f0 = (const float*)d_in[0];
    const float* f1 = (const float*)d_in[1];
    const float* f2 = (const float*)d_in[2];
    const float* f3 = (const float*)d_in[3];
    // d_in[4] = feat4 (13x13) — never selected by the 4 RATIOS; unused.
    const float* p0 = (const float*)d_in[5];
    const float* p1 = (const float*)d_in[6];
    float* out = (float*)d_out;

    setup_kernel<<<4, 256>>>(p0, p1);
    dim3 grid(4, NROI);
    pool_kernel<<<grid, 256>>>(f0, f1, f2, f3, out);
}

// round 13
// speedup vs baseline: 2.7439x; 2.7439x over previous
#include <cuda_runtime.h>
#include <cuda_bf16.h>

#define RES 7
#define NROI 1024
#define NCH 256

// ---------------- per-roi precomputed tables ----------------
__device__ int2   g_lb[NROI];          // lvl, batch
__device__ int4   g_yrow[NROI][8];     // 4 row offsets (premultiplied by W) per py
__device__ float4 g_ywt[NROI][8];      // y weights (*0.5, validity folded)
__device__ int4   g_xcol[NROI][8];     // 4 col offsets per px
__device__ float4 g_xwt[NROI][8];      // x weights (*0.5, validity folded)

__device__ __forceinline__ void samp(float v, int size,
                                     int& lo, int& hi, float& wl, float& wh) {
    bool valid = (v >= -1.0f) && (v <= (float)size);
    float v0 = fmaxf(v, 0.0f);
    int l = (int)floorf(v0);
    float fr;
    if (l >= size - 1) { l = size - 1; hi = size - 1; fr = 0.0f; }
    else               { hi = l + 1; fr = v0 - (float)l; }
    lo = l;
    wl = valid ? (1.0f - fr) : 0.0f;
    wh = valid ? fr : 0.0f;
}

__global__ void setup_kernel(const float* __restrict__ p0,
                             const float* __restrict__ p1) {
    int r = blockIdx.x * blockDim.x + threadIdx.x;
    if (r >= NROI) return;
    const float* p = (r < 512) ? (p0 + r * 4) : (p1 + (r - 512) * 4);
    float x1 = p[0], y1 = p[1], x2 = p[2], y2 = p[3];
    float area = (x2 - x1 + 1.0f) * (y2 - y1 + 1.0f);
    float sz = sqrtf(area);
    float lv = floorf(4.0f + log2f(sz / 224.0f + 1e-6f));
    lv = fminf(fmaxf(lv, 2.0f), 5.0f);
    int lvl = (int)lv - 2;
    float scale = 0.25f / (float)(1 << lvl);
    int H, W;
    switch (lvl) {
        case 0:  H = 200; W = 200; break;
        case 1:  H = 100; W = 100; break;
        case 2:  H = 50;  W = 50;  break;
        default: H = 25;  W = 25;  break;
    }
    float x1s = x1 * scale, y1s = y1 * scale;
    float rw = fmaxf(x2 * scale - x1s, 1.0f);
    float rh = fmaxf(y2 * scale - y1s, 1.0f);
    float bw = rw / 7.0f, bh = rh / 7.0f;

    g_lb[r] = make_int2(lvl, (r < 512) ? 0 : 1);

#pragma unroll
    for (int q = 0; q < 7; q++) {
        {   // y samples 2q, 2q+1
            float s0 = y1s + ((float)(2 * q) + 0.5f) * 0.5f * bh;
            float s1 = y1s + ((float)(2 * q + 1) + 0.5f) * 0.5f * bh;
            int l0, h0, l1, h1; float a0, b0, a1, b1;
            samp(s0, H, l0, h0, a0, b0);
            samp(s1, H, l1, h1, a1, b1);
            g_yrow[r][q] = make_int4(l0 * W, h0 * W, l1 * W, h1 * W);
            g_ywt[r][q]  = make_float4(a0 * 0.5f, b0 * 0.5f, a1 * 0.5f, b1 * 0.5f);
        }
        {   // x samples 2q, 2q+1
            float s0 = x1s + ((float)(2 * q) + 0.5f) * 0.5f * bw;
            float s1 = x1s + ((float)(2 * q + 1) + 0.5f) * 0.5f * bw;
            int l0, h0, l1, h1; float a0, b0, a1, b1;
            samp(s0, W, l0, h0, a0, b0);
            samp(s1, W, l1, h1, a1, b1);
            g_xcol[r][q] = make_int4(l0, h0, l1, h1);
            g_xwt[r][q]  = make_float4(a0 * 0.5f, b0 * 0.5f, a1 * 0.5f, b1 * 0.5f);
        }
    }
}

// grid = (25, NROI): blockIdx.y = roi; e in [0, 6272) = (c in [0,128), bin).
// Each thread computes bin for channels c and c+128 (same taps, 32 LDGs in flight).
__global__ __launch_bounds__(256) void pool_kernel(
    const float* __restrict__ f0, const float* __restrict__ f1,
    const float* __restrict__ f2, const float* __restrict__ f3,
    float* __restrict__ out) {

    __shared__ int4   yoS[8];
    __shared__ float4 ywS[8];
    __shared__ int4   xoS[8];
    __shared__ float4 xwS[8];

    const int roi = blockIdx.y;
    const int tid = threadIdx.x;
    if (tid < 8) {
        yoS[tid] = g_yrow[roi][tid];
        ywS[tid] = g_ywt[roi][tid];
        xoS[tid] = g_xcol[roi][tid];
        xwS[tid] = g_xwt[roi][tid];
    }
    __syncthreads();

    const int e = blockIdx.x * 256 + tid;   // [0, 6272)
    if (e >= 6272) return;
    const int c = e / 49;                   // [0, 128)
    const int bin = e - c * 49;
    const int py = bin / 7;
    const int px = bin - py * 7;

    const int2 lb = g_lb[roi];
    const float* base; int HW;
    switch (lb.x) {
        case 0:  base = f0; HW = 200 * 200; break;
        case 1:  base = f1; HW = 100 * 100; break;
        case 2:  base = f2; HW = 50 * 50;   break;
        default: base = f3; HW = 25 * 25;   break;
    }

    const int4   yr = yoS[py];
    const float4 wy = ywS[py];
    const int4   xc = xoS[px];
    const float4 wx = xwS[px];

    const float* cb0 = base + ((size_t)lb.y * NCH + c) * HW;
    const float* cb1 = cb0 + (size_t)128 * HW;

    // channel c
    const float* a0 = cb0 + yr.x; const float* a1 = cb0 + yr.y;
    const float* a2 = cb0 + yr.z; const float* a3 = cb0 + yr.w;
    // channel c+128
    const float* b0 = cb1 + yr.x; const float* b1 = cb1 + yr.y;
    const float* b2 = cb1 + yr.z; const float* b3 = cb1 + yr.w;

    float s0 = wx.x * __ldg(a0 + xc.x) + wx.y * __ldg(a0 + xc.y)
             + wx.z * __ldg(a0 + xc.z) + wx.w * __ldg(a0 + xc.w);
    float t0 = wx.x * __ldg(b0 + xc.x) + wx.y * __ldg(b0 + xc.y)
             + wx.z * __ldg(b0 + xc.z) + wx.w * __ldg(b0 + xc.w);
    float s1 = wx.x * __ldg(a1 + xc.x) + wx.y * __ldg(a1 + xc.y)
             + wx.z * __ldg(a1 + xc.z) + wx.w * __ldg(a1 + xc.w);
    float t1 = wx.x * __ldg(b1 + xc.x) + wx.y * __ldg(b1 + xc.y)
             + wx.z * __ldg(b1 + xc.z) + wx.w * __ldg(b1 + xc.w);
    float s2 = wx.x * __ldg(a2 + xc.x) + wx.y * __ldg(a2 + xc.y)
             + wx.z * __ldg(a2 + xc.z) + wx.w * __ldg(a2 + xc.w);
    float t2 = wx.x * __ldg(b2 + xc.x) + wx.y * __ldg(b2 + xc.y)
             + wx.z * __ldg(b2 + xc.z) + wx.w * __ldg(b2 + xc.w);
    float s3 = wx.x * __ldg(a3 + xc.x) + wx.y * __ldg(a3 + xc.y)
             + wx.z * __ldg(a3 + xc.z) + wx.w * __ldg(a3 + xc.w);
    float t3 = wx.x * __ldg(b3 + xc.x) + wx.y * __ldg(b3 + xc.y)
             + wx.z * __ldg(b3 + xc.z) + wx.w * __ldg(b3 + xc.w);

    float accA = wy.x * s0 + wy.y * s1 + wy.z * s2 + wy.w * s3;
    float accB = wy.x * t0 + wy.y * t1 + wy.z * t2 + wy.w * t3;

    size_t o = ((size_t)roi * NCH + c) * 49 + bin;
    out[o] = accA;
    out[o + (size_t)128 * 49] = accB;
}

extern "C" void kernel_launch(void* const* d_in, const int* in_sizes, int n_in,
                              void* d_out, int out_size) {
    const float* f0 = (const float*)d_in[0];
    const float* f1 = (const float*)d_in[1];
    const float* f2 = (const float*)d_in[2];
    const float* f3 = (const float*)d_in[3];
    // d_in[4] = feat4 (13x13) — never selected by the 4 RATIOS; unused.
    const float* p0 = (const float*)d_in[5];
    const float* p1 = (const float*)d_in[6];
    float* out = (float*)d_out;

    setup_kernel<<<4, 256>>>(p0, p1);
    dim3 grid(25, NROI);
    pool_kernel<<<grid, 256>>>(f0, f1, f2, f3, out);
}